// round 2
// baseline (speedup 1.0000x reference)
#include <cuda_runtime.h>
#include <cuda_bf16.h>
#include <cstddef>

// Problem constants
#define N_NODES 50000
#define C_DIM   64
#define HID_DIM 128
#define R_DIM   16
#define B_DIM   2
#define L_DIM   12
#define E_EDGES 1600000
#define T_DIM   8
#define M_ROWS  (B_DIM * N_NODES)   // 100000

// Scratch tables: a[b][n][16], b[b][n][16] flattened as row m = b*N + n.
// Stored as float4 so gathers are 16B-aligned vector loads.
__device__ float4 g_a[M_ROWS * 4];
__device__ float4 g_b[M_ROWS * 4];

// ---------------------------------------------------------------------------
// Kernel 1: fused two-layer MLP for both weight sets.
// Tile: 64 rows x full widths. 256 threads, 4x8 register tile for layer 1.
// ---------------------------------------------------------------------------
__global__ __launch_bounds__(256, 2)
void mlp_kernel(const float* __restrict__ X,
                const float* __restrict__ W1s, const float* __restrict__ b1s,
                const float* __restrict__ W2s, const float* __restrict__ b2s,
                const float* __restrict__ W1d, const float* __restrict__ b1d,
                const float* __restrict__ W2d, const float* __restrict__ b2d)
{
    extern __shared__ float sh[];
    float* Hs   = sh;                      // 64 * 65
    float* Ws   = Hs  + 64 * 65;           // 64 * 128
    float* Hid  = Ws  + 64 * 128;          // 64 * 129
    float* W2sh = Hid + 64 * 129;          // 128 * 16

    const int tid = threadIdx.x;
    const int m0  = blockIdx.x * 64;

    // Load H tile: rows m0..m0+63 of H (= X[:, T-1]) -> Hs[64][65]
    for (int i = tid; i < 64 * 64; i += 256) {
        int r = i >> 6, c = i & 63;
        int m = m0 + r;
        float v = 0.0f;
        if (m < M_ROWS) {
            int b = m / N_NODES;
            int n = m - b * N_NODES;
            v = X[(((size_t)b * T_DIM + (T_DIM - 1)) * N_NODES + n) * C_DIM + c];
        }
        Hs[r * 65 + c] = v;
    }
    __syncthreads();

    const int ty = tid >> 4;   // 0..15 -> row group (4 rows)
    const int tx = tid & 15;   // 0..15 -> col group (8 cols)

    #pragma unroll
    for (int set = 0; set < 2; set++) {
        const float* W1 = set ? W1d : W1s;
        const float* b1 = set ? b1d : b1s;
        const float* W2 = set ? W2d : W2s;
        const float* b2 = set ? b2d : b2s;
        float4* outTab  = set ? g_b : g_a;

        for (int i = tid; i < 64 * 128; i += 256) Ws[i]   = W1[i];
        for (int i = tid; i < 128 * 16; i += 256) W2sh[i] = W2[i];
        __syncthreads();

        // Layer 1: 64x64 @ 64x128 register-tiled
        float acc[4][8];
        #pragma unroll
        for (int i = 0; i < 4; i++)
            #pragma unroll
            for (int j = 0; j < 8; j++) acc[i][j] = 0.0f;

        #pragma unroll 4
        for (int k = 0; k < 64; k++) {
            float hv[4], wv[8];
            #pragma unroll
            for (int i = 0; i < 4; i++) hv[i] = Hs[(ty * 4 + i) * 65 + k];
            #pragma unroll
            for (int j = 0; j < 8; j++) wv[j] = Ws[k * 128 + tx * 8 + j];
            #pragma unroll
            for (int i = 0; i < 4; i++)
                #pragma unroll
                for (int j = 0; j < 8; j++) acc[i][j] += hv[i] * wv[j];
        }

        // bias + relu -> Hid shared
        #pragma unroll
        for (int j = 0; j < 8; j++) {
            float bb = __ldg(&b1[tx * 8 + j]);
            #pragma unroll
            for (int i = 0; i < 4; i++) {
                float v = acc[i][j] + bb;
                Hid[(ty * 4 + i) * 129 + tx * 8 + j] = v > 0.0f ? v : 0.0f;
            }
        }
        __syncthreads();

        // Layer 2: 64x128 @ 128x16. Thread -> (row = tid/4, 4 r-outputs).
        {
            int row = tid >> 2;
            int rg  = (tid & 3) * 4;
            float acc2[4];
            #pragma unroll
            for (int j = 0; j < 4; j++) acc2[j] = __ldg(&b2[rg + j]);

            #pragma unroll 4
            for (int k = 0; k < 128; k++) {
                float hv = Hid[row * 129 + k];
                #pragma unroll
                for (int j = 0; j < 4; j++) acc2[j] += hv * W2sh[k * 16 + rg + j];
            }
            int m = m0 + row;
            if (m < M_ROWS) {
                float4 v;
                v.x = acc2[0]; v.y = acc2[1]; v.z = acc2[2]; v.w = acc2[3];
                outTab[(size_t)m * 4 + (tid & 3)] = v;
            }
        }
        __syncthreads();
    }
}

// ---------------------------------------------------------------------------
// Kernel 2: per-edge gather + low-rank bilinear contraction.
// logits[b,l,e] = sum_r a[b,I[e],r] * gamma[l,r] * b[b,J[e],r]
// One thread per edge. Output stores coalesced (consecutive e per (b,l)).
// NOTE: edge_index comes in as int32 (JAX x64 disabled).
// ---------------------------------------------------------------------------
__global__ __launch_bounds__(256)
void edge_kernel(const int* __restrict__ eidx,
                 const float* __restrict__ gamma,
                 float* __restrict__ out)
{
    __shared__ float g[L_DIM * R_DIM];
    const int tid = threadIdx.x;
    if (tid < L_DIM * R_DIM) g[tid] = gamma[tid];
    __syncthreads();

    const long long e = (long long)blockIdx.x * blockDim.x + tid;
    if (e >= E_EDGES) return;

    const int I = eidx[e];
    const int J = eidx[(size_t)E_EDGES + e];

    #pragma unroll
    for (int b = 0; b < B_DIM; b++) {
        const float4* ap = g_a + ((size_t)b * N_NODES + I) * 4;
        const float4* bp = g_b + ((size_t)b * N_NODES + J) * 4;

        float p[16];
        #pragma unroll
        for (int q = 0; q < 4; q++) {
            float4 av = ap[q];
            float4 bv = bp[q];
            p[q * 4 + 0] = av.x * bv.x;
            p[q * 4 + 1] = av.y * bv.y;
            p[q * 4 + 2] = av.z * bv.z;
            p[q * 4 + 3] = av.w * bv.w;
        }

        #pragma unroll
        for (int l = 0; l < L_DIM; l++) {
            float s = 0.0f;
            #pragma unroll
            for (int r = 0; r < R_DIM; r++) s += g[l * R_DIM + r] * p[r];
            out[((size_t)(b * L_DIM + l)) * E_EDGES + e] = s;
        }
    }
}

// ---------------------------------------------------------------------------
// Launch
// ---------------------------------------------------------------------------
extern "C" void kernel_launch(void* const* d_in, const int* in_sizes, int n_in,
                              void* d_out, int out_size)
{
    const float* X    = (const float*)d_in[0];
    const int*   eidx = (const int*)d_in[1];
    const float* W1s  = (const float*)d_in[2];
    const float* b1s  = (const float*)d_in[3];
    const float* W2s  = (const float*)d_in[4];
    const float* b2s  = (const float*)d_in[5];
    const float* W1d  = (const float*)d_in[6];
    const float* b1d  = (const float*)d_in[7];
    const float* W2d  = (const float*)d_in[8];
    const float* b2d  = (const float*)d_in[9];
    const float* gamma= (const float*)d_in[10];
    float* out = (float*)d_out;

    // Dynamic shared size for MLP kernel
    const int smem = (64 * 65 + 64 * 128 + 64 * 129 + 128 * 16) * (int)sizeof(float);
    cudaFuncSetAttribute(mlp_kernel, cudaFuncAttributeMaxDynamicSharedMemorySize, smem);

    const int blocks1 = (M_ROWS + 63) / 64;
    mlp_kernel<<<blocks1, 256, smem>>>(X, W1s, b1s, W2s, b2s, W1d, b1d, W2d, b2d);

    const int blocks2 = (E_EDGES + 255) / 256;
    edge_kernel<<<blocks2, 256>>>(eidx, gamma, out);
}

// round 3
// speedup vs baseline: 1.0830x; 1.0830x over previous
#include <cuda_runtime.h>
#include <cuda_bf16.h>
#include <cstddef>

#define N_NODES 50000
#define C_DIM   64
#define HID_DIM 128
#define R_DIM   16
#define B_DIM   2
#define L_DIM   12
#define E_EDGES 1600000
#define T_DIM   8
#define M_ROWS  (B_DIM * N_NODES)   // 100000

// Scratch tables: row m = b*N + n, 4 float4 (16 floats) per row.
__device__ float4 g_a[M_ROWS * 4];
__device__ float4 g_b[M_ROWS * 4];

// ---------------------------------------------------------------------------
// Kernel 1: fused two-layer MLP for both weight sets.
// 128-row tile, 512 threads. Layer 1: 4x8 register tile, all-vector LDS.
// ---------------------------------------------------------------------------
#define MLP_ROWS 128
#define RS 132            // padded row stride for transposed tiles

__global__ __launch_bounds__(512, 1)
void mlp_kernel(const float* __restrict__ X,
                const float* __restrict__ W1s, const float* __restrict__ b1s,
                const float* __restrict__ W2s, const float* __restrict__ b2s,
                const float* __restrict__ W1d, const float* __restrict__ b1d,
                const float* __restrict__ W2d, const float* __restrict__ b2d)
{
    extern __shared__ float sh[];
    float* HsT  = sh;                       // [64][RS]   H transposed (k-major)
    float* Ws   = HsT + 64 * RS;            // [64][128]  W1
    float* HidT = Ws + 64 * 128;            // [128][RS]  hidden transposed
    float* W2sh = HidT + 128 * RS;          // [128][16]

    const int tid = threadIdx.x;
    const int m0  = blockIdx.x * MLP_ROWS;

    // Load H tile transposed: HsT[c][r] = X[b, T-1, n, c], m = m0 + r
    {
        for (int u = 0; u < 4; u++) {
            int id = tid + 512 * u;           // 2048 float4 = 128 rows x 16 f4
            int r  = id >> 4;
            int cg = id & 15;
            int m  = m0 + r;
            float4 v = make_float4(0.f, 0.f, 0.f, 0.f);
            if (m < M_ROWS) {
                int b = m / N_NODES;
                int n = m - b * N_NODES;
                v = *(const float4*)&X[(((size_t)b * T_DIM + (T_DIM - 1)) * N_NODES + n) * C_DIM + cg * 4];
            }
            HsT[(cg * 4 + 0) * RS + r] = v.x;
            HsT[(cg * 4 + 1) * RS + r] = v.y;
            HsT[(cg * 4 + 2) * RS + r] = v.z;
            HsT[(cg * 4 + 3) * RS + r] = v.w;
        }
    }
    __syncthreads();

    const int ty = tid >> 4;    // 0..31 -> 4-row group
    const int tx = tid & 15;    // 0..15 -> 8-col group

    #pragma unroll
    for (int set = 0; set < 2; set++) {
        const float* W1 = set ? W1d : W1s;
        const float* b1 = set ? b1d : b1s;
        const float* W2 = set ? W2d : W2s;
        const float* b2 = set ? b2d : b2s;
        float4* outTab  = set ? g_b : g_a;

        // Stage weights (vectorized)
        for (int i = tid; i < 64 * 128 / 4; i += 512)
            ((float4*)Ws)[i] = ((const float4*)W1)[i];
        for (int i = tid; i < 128 * 16 / 4; i += 512)
            ((float4*)W2sh)[i] = ((const float4*)W2)[i];
        __syncthreads();

        // Layer 1: 128x64 @ 64x128, 4x8 per thread, vector LDS only.
        float acc[4][8];
        #pragma unroll
        for (int i = 0; i < 4; i++)
            #pragma unroll
            for (int j = 0; j < 8; j++) acc[i][j] = 0.0f;

        #pragma unroll 8
        for (int k = 0; k < 64; k++) {
            float4 hv  = *(const float4*)&HsT[k * RS + ty * 4];
            float4 wv0 = *(const float4*)&Ws[k * 128 + tx * 8];
            float4 wv1 = *(const float4*)&Ws[k * 128 + tx * 8 + 4];
            float h[4] = {hv.x, hv.y, hv.z, hv.w};
            float w[8] = {wv0.x, wv0.y, wv0.z, wv0.w, wv1.x, wv1.y, wv1.z, wv1.w};
            #pragma unroll
            for (int i = 0; i < 4; i++)
                #pragma unroll
                for (int j = 0; j < 8; j++) acc[i][j] += h[i] * w[j];
        }

        // bias + relu -> HidT[c][r]
        #pragma unroll
        for (int j = 0; j < 8; j++) {
            float bb = __ldg(&b1[tx * 8 + j]);
            #pragma unroll
            for (int i = 0; i < 4; i++) {
                float v = acc[i][j] + bb;
                HidT[(tx * 8 + j) * RS + ty * 4 + i] = v > 0.0f ? v : 0.0f;
            }
        }
        __syncthreads();

        // Layer 2: 128x128 @ 128x16. thread -> (row = tid>>2, 4 r cols)
        {
            int row = tid >> 2;           // 0..127
            int rg  = (tid & 3) * 4;
            float acc2[4];
            #pragma unroll
            for (int j = 0; j < 4; j++) acc2[j] = __ldg(&b2[rg + j]);

            #pragma unroll 8
            for (int k = 0; k < 128; k++) {
                float hv = HidT[k * RS + row];
                float4 wv = *(const float4*)&W2sh[k * 16 + rg];
                acc2[0] += hv * wv.x;
                acc2[1] += hv * wv.y;
                acc2[2] += hv * wv.z;
                acc2[3] += hv * wv.w;
            }
            int m = m0 + row;
            if (m < M_ROWS) {
                float4 v; v.x = acc2[0]; v.y = acc2[1]; v.z = acc2[2]; v.w = acc2[3];
                outTab[(size_t)m * 4 + (tid & 3)] = v;
            }
        }
        __syncthreads();
    }
}

// ---------------------------------------------------------------------------
// Kernel 2: CTA-staged edge scoring. 128 edges per block, 256 threads.
//  Phase 1: coalesced gather (4 lanes share a 64B row) -> smem
//  Phase 2: per-(edge,batch) bilinear contraction -> smem out stage
//  Phase 3: float4 coalesced stores
// ---------------------------------------------------------------------------
#define EPB 128          // edges per block
#define RAW_STRIDE 17    // float4 per edge in raw stage (16 + 1 pad)

__global__ __launch_bounds__(256)
void edge_kernel(const int* __restrict__ eidx,
                 const float* __restrict__ gamma,
                 float* __restrict__ out)
{
    extern __shared__ float esh[];
    float4* raw     = (float4*)esh;                       // [EPB][17] float4
    float*  ostage  = esh + EPB * RAW_STRIDE * 4;         // [24][EPB]
    int*    sI      = (int*)(ostage + 24 * EPB);          // [EPB]
    int*    sJ      = sI + EPB;                           // [EPB]
    float*  g       = (float*)(sJ + EPB);                 // [12][16]

    const int tid = threadIdx.x;
    const int e0  = blockIdx.x * EPB;

    if (tid < EPB)            sI[tid]       = eidx[e0 + tid];
    else                      sJ[tid - EPB] = eidx[(size_t)E_EDGES + e0 + tid - EPB];
    if (tid < L_DIM * R_DIM)  g[tid] = gamma[tid];
    __syncthreads();

    // Phase 1: gather. 2048 float4, 8 per thread.
    // gid = tid + 256*u: edge=gid>>4, sub=gid&15 -> tab(1) bb(1) q(2)
    {
        float4 regs[8];
        int    dsts[8];
        #pragma unroll
        for (int u = 0; u < 8; u++) {
            int gid  = tid + 256 * u;
            int edge = gid >> 4;
            int sub  = gid & 15;
            int tab  = sub >> 3;
            int bb   = (sub >> 2) & 1;
            int q    = sub & 3;
            int node = tab ? sJ[edge] : sI[edge];
            const float4* table = tab ? g_b : g_a;
            regs[u] = table[((size_t)bb * N_NODES + node) * 4 + q];
            dsts[u] = edge * RAW_STRIDE + sub;
        }
        #pragma unroll
        for (int u = 0; u < 8; u++) raw[dsts[u]] = regs[u];
    }
    __syncthreads();

    // Phase 2: compute. thread -> (bb = tid>>7, e = tid&127)
    {
        int bb = tid >> 7;
        int e  = tid & 127;
        const float4* base = raw + e * RAW_STRIDE + bb * 4;
        float p[16];
        #pragma unroll
        for (int q = 0; q < 4; q++) {
            float4 av = base[q];       // a row quad
            float4 bv = base[8 + q];   // b row quad
            p[q * 4 + 0] = av.x * bv.x;
            p[q * 4 + 1] = av.y * bv.y;
            p[q * 4 + 2] = av.z * bv.z;
            p[q * 4 + 3] = av.w * bv.w;
        }
        #pragma unroll
        for (int l = 0; l < L_DIM; l++) {
            float s = 0.0f;
            #pragma unroll
            for (int r = 0; r < R_DIM; r++) s += g[l * R_DIM + r] * p[r];
            ostage[(bb * L_DIM + l) * EPB + e] = s;
        }
    }
    __syncthreads();

    // Phase 3: store. 24 rows x 128 floats = 768 float4, 3 per thread.
    {
        #pragma unroll
        for (int u = 0; u < 3; u++) {
            int f4id = tid + 256 * u;
            int row  = f4id >> 5;          // 0..23  (= b*L + l)
            int col  = f4id & 31;
            float4 v = *(const float4*)&ostage[row * EPB + col * 4];
            *(float4*)&out[(size_t)row * E_EDGES + e0 + col * 4] = v;
        }
    }
}

// ---------------------------------------------------------------------------
// Launch
// ---------------------------------------------------------------------------
extern "C" void kernel_launch(void* const* d_in, const int* in_sizes, int n_in,
                              void* d_out, int out_size)
{
    const float* X    = (const float*)d_in[0];
    const int*   eidx = (const int*)d_in[1];
    const float* W1s  = (const float*)d_in[2];
    const float* b1s  = (const float*)d_in[3];
    const float* W2s  = (const float*)d_in[4];
    const float* b2s  = (const float*)d_in[5];
    const float* W1d  = (const float*)d_in[6];
    const float* b1d  = (const float*)d_in[7];
    const float* W2d  = (const float*)d_in[8];
    const float* b2d  = (const float*)d_in[9];
    const float* gamma= (const float*)d_in[10];
    float* out = (float*)d_out;

    const int mlp_smem = (64 * RS + 64 * 128 + 128 * RS + 128 * 16) * (int)sizeof(float);
    static bool attr_done = false;
    const int edge_smem = (EPB * RAW_STRIDE * 4 + 24 * EPB) * (int)sizeof(float)
                          + 2 * EPB * (int)sizeof(int) + L_DIM * R_DIM * (int)sizeof(float);
    if (!attr_done) {
        cudaFuncSetAttribute(mlp_kernel, cudaFuncAttributeMaxDynamicSharedMemorySize, mlp_smem);
        cudaFuncSetAttribute(edge_kernel, cudaFuncAttributeMaxDynamicSharedMemorySize, edge_smem);
        attr_done = true;
    }

    const int blocks1 = (M_ROWS + MLP_ROWS - 1) / MLP_ROWS;
    mlp_kernel<<<blocks1, 512, mlp_smem>>>(X, W1s, b1s, W2s, b2s, W1d, b1d, W2d, b2d);

    const int blocks2 = E_EDGES / EPB;
    edge_kernel<<<blocks2, 256, edge_smem>>>(eidx, gamma, out);
}

// round 4
// speedup vs baseline: 1.0859x; 1.0027x over previous
#include <cuda_runtime.h>
#include <cuda_bf16.h>
#include <cstddef>

#define N_NODES 50000
#define C_DIM   64
#define HID_DIM 128
#define R_DIM   16
#define B_DIM   2
#define L_DIM   12
#define E_EDGES 1600000
#define T_DIM   8
#define M_ROWS  (B_DIM * N_NODES)   // 100000

// Scratch tables: row m = b*N + n, 4 float4 (16 floats) per row.
__device__ float4 g_a[M_ROWS * 4];
__device__ float4 g_b[M_ROWS * 4];

// ---------------------------------------------------------------------------
// Kernel 1: fused two-layer MLP for both weight sets.
// 128-row tile, 512 threads. Layer 1: 4x8 register tile, all-vector LDS.
// ---------------------------------------------------------------------------
#define MLP_ROWS 128
#define RS 132            // padded row stride for transposed tiles

__global__ __launch_bounds__(512, 1)
void mlp_kernel(const float* __restrict__ X,
                const float* __restrict__ W1s, const float* __restrict__ b1s,
                const float* __restrict__ W2s, const float* __restrict__ b2s,
                const float* __restrict__ W1d, const float* __restrict__ b1d,
                const float* __restrict__ W2d, const float* __restrict__ b2d)
{
    extern __shared__ float sh[];
    float* HsT  = sh;                       // [64][RS]   H transposed (k-major)
    float* Ws   = HsT + 64 * RS;            // [64][128]  W1
    float* HidT = Ws + 64 * 128;            // [128][RS]  hidden transposed
    float* W2sh = HidT + 128 * RS;          // [128][16]

    const int tid = threadIdx.x;
    const int m0  = blockIdx.x * MLP_ROWS;

    // Load H tile transposed: HsT[c][r] = X[b, T-1, n, c], m = m0 + r
    {
        for (int u = 0; u < 4; u++) {
            int id = tid + 512 * u;           // 2048 float4 = 128 rows x 16 f4
            int r  = id >> 4;
            int cg = id & 15;
            int m  = m0 + r;
            float4 v = make_float4(0.f, 0.f, 0.f, 0.f);
            if (m < M_ROWS) {
                int b = m / N_NODES;
                int n = m - b * N_NODES;
                v = *(const float4*)&X[(((size_t)b * T_DIM + (T_DIM - 1)) * N_NODES + n) * C_DIM + cg * 4];
            }
            HsT[(cg * 4 + 0) * RS + r] = v.x;
            HsT[(cg * 4 + 1) * RS + r] = v.y;
            HsT[(cg * 4 + 2) * RS + r] = v.z;
            HsT[(cg * 4 + 3) * RS + r] = v.w;
        }
    }
    __syncthreads();

    const int ty = tid >> 4;    // 0..31 -> 4-row group
    const int tx = tid & 15;    // 0..15 -> 8-col group

    #pragma unroll
    for (int set = 0; set < 2; set++) {
        const float* W1 = set ? W1d : W1s;
        const float* b1 = set ? b1d : b1s;
        const float* W2 = set ? W2d : W2s;
        const float* b2 = set ? b2d : b2s;
        float4* outTab  = set ? g_b : g_a;

        // Stage weights (vectorized)
        for (int i = tid; i < 64 * 128 / 4; i += 512)
            ((float4*)Ws)[i] = ((const float4*)W1)[i];
        for (int i = tid; i < 128 * 16 / 4; i += 512)
            ((float4*)W2sh)[i] = ((const float4*)W2)[i];
        __syncthreads();

        // Layer 1: 128x64 @ 64x128, 4x8 per thread, vector LDS only.
        float acc[4][8];
        #pragma unroll
        for (int i = 0; i < 4; i++)
            #pragma unroll
            for (int j = 0; j < 8; j++) acc[i][j] = 0.0f;

        #pragma unroll 8
        for (int k = 0; k < 64; k++) {
            float4 hv  = *(const float4*)&HsT[k * RS + ty * 4];
            float4 wv0 = *(const float4*)&Ws[k * 128 + tx * 8];
            float4 wv1 = *(const float4*)&Ws[k * 128 + tx * 8 + 4];
            float h[4] = {hv.x, hv.y, hv.z, hv.w};
            float w[8] = {wv0.x, wv0.y, wv0.z, wv0.w, wv1.x, wv1.y, wv1.z, wv1.w};
            #pragma unroll
            for (int i = 0; i < 4; i++)
                #pragma unroll
                for (int j = 0; j < 8; j++) acc[i][j] += h[i] * w[j];
        }

        // bias + relu -> HidT[c][r]
        #pragma unroll
        for (int j = 0; j < 8; j++) {
            float bb = __ldg(&b1[tx * 8 + j]);
            #pragma unroll
            for (int i = 0; i < 4; i++) {
                float v = acc[i][j] + bb;
                HidT[(tx * 8 + j) * RS + ty * 4 + i] = v > 0.0f ? v : 0.0f;
            }
        }
        __syncthreads();

        // Layer 2: 128x128 @ 128x16. thread -> (row = tid>>2, 4 r cols)
        {
            int row = tid >> 2;           // 0..127
            int rg  = (tid & 3) * 4;
            float acc2[4];
            #pragma unroll
            for (int j = 0; j < 4; j++) acc2[j] = __ldg(&b2[rg + j]);

            #pragma unroll 8
            for (int k = 0; k < 128; k++) {
                float hv = HidT[k * RS + row];
                float4 wv = *(const float4*)&W2sh[k * 16 + rg];
                acc2[0] += hv * wv.x;
                acc2[1] += hv * wv.y;
                acc2[2] += hv * wv.z;
                acc2[3] += hv * wv.w;
            }
            int m = m0 + row;
            if (m < M_ROWS) {
                float4 v; v.x = acc2[0]; v.y = acc2[1]; v.z = acc2[2]; v.w = acc2[3];
                outTab[(size_t)m * 4 + (tid & 3)] = v;
            }
        }
        __syncthreads();
    }
}

// ---------------------------------------------------------------------------
// Kernel 2: CTA-staged edge scoring. 128 edges per block, 256 threads.
//  Phase 1: coalesced gather (4 lanes share a 64B row) -> smem
//  Phase 2: per-(edge,batch) bilinear contraction -> smem out stage
//  Phase 3: float4 coalesced stores
// ---------------------------------------------------------------------------
#define EPB 128          // edges per block
#define RAW_STRIDE 17    // float4 per edge in raw stage (16 + 1 pad)

__global__ __launch_bounds__(256)
void edge_kernel(const int* __restrict__ eidx,
                 const float* __restrict__ gamma,
                 float* __restrict__ out)
{
    extern __shared__ float esh[];
    float4* raw     = (float4*)esh;                       // [EPB][17] float4
    float*  ostage  = esh + EPB * RAW_STRIDE * 4;         // [24][EPB]
    int*    sI      = (int*)(ostage + 24 * EPB);          // [EPB]
    int*    sJ      = sI + EPB;                           // [EPB]
    float*  g       = (float*)(sJ + EPB);                 // [12][16]

    const int tid = threadIdx.x;
    const int e0  = blockIdx.x * EPB;

    if (tid < EPB)            sI[tid]       = eidx[e0 + tid];
    else                      sJ[tid - EPB] = eidx[(size_t)E_EDGES + e0 + tid - EPB];
    if (tid < L_DIM * R_DIM)  g[tid] = gamma[tid];
    __syncthreads();

    // Phase 1: gather. 2048 float4, 8 per thread.
    // gid = tid + 256*u: edge=gid>>4, sub=gid&15 -> tab(1) bb(1) q(2)
    {
        float4 regs[8];
        int    dsts[8];
        #pragma unroll
        for (int u = 0; u < 8; u++) {
            int gid  = tid + 256 * u;
            int edge = gid >> 4;
            int sub  = gid & 15;
            int tab  = sub >> 3;
            int bb   = (sub >> 2) & 1;
            int q    = sub & 3;
            int node = tab ? sJ[edge] : sI[edge];
            const float4* table = tab ? g_b : g_a;
            regs[u] = table[((size_t)bb * N_NODES + node) * 4 + q];
            dsts[u] = edge * RAW_STRIDE + sub;
        }
        #pragma unroll
        for (int u = 0; u < 8; u++) raw[dsts[u]] = regs[u];
    }
    __syncthreads();

    // Phase 2: compute. thread -> (bb = tid>>7, e = tid&127)
    {
        int bb = tid >> 7;
        int e  = tid & 127;
        const float4* base = raw + e * RAW_STRIDE + bb * 4;
        float p[16];
        #pragma unroll
        for (int q = 0; q < 4; q++) {
            float4 av = base[q];       // a row quad
            float4 bv = base[8 + q];   // b row quad
            p[q * 4 + 0] = av.x * bv.x;
            p[q * 4 + 1] = av.y * bv.y;
            p[q * 4 + 2] = av.z * bv.z;
            p[q * 4 + 3] = av.w * bv.w;
        }
        #pragma unroll
        for (int l = 0; l < L_DIM; l++) {
            float s = 0.0f;
            #pragma unroll
            for (int r = 0; r < R_DIM; r++) s += g[l * R_DIM + r] * p[r];
            ostage[(bb * L_DIM + l) * EPB + e] = s;
        }
    }
    __syncthreads();

    // Phase 3: store. 24 rows x 128 floats = 768 float4, 3 per thread.
    {
        #pragma unroll
        for (int u = 0; u < 3; u++) {
            int f4id = tid + 256 * u;
            int row  = f4id >> 5;          // 0..23  (= b*L + l)
            int col  = f4id & 31;
            float4 v = *(const float4*)&ostage[row * EPB + col * 4];
            *(float4*)&out[(size_t)row * E_EDGES + e0 + col * 4] = v;
        }
    }
}

// ---------------------------------------------------------------------------
// Launch
// ---------------------------------------------------------------------------
extern "C" void kernel_launch(void* const* d_in, const int* in_sizes, int n_in,
                              void* d_out, int out_size)
{
    const float* X    = (const float*)d_in[0];
    const int*   eidx = (const int*)d_in[1];
    const float* W1s  = (const float*)d_in[2];
    const float* b1s  = (const float*)d_in[3];
    const float* W2s  = (const float*)d_in[4];
    const float* b2s  = (const float*)d_in[5];
    const float* W1d  = (const float*)d_in[6];
    const float* b1d  = (const float*)d_in[7];
    const float* W2d  = (const float*)d_in[8];
    const float* b2d  = (const float*)d_in[9];
    const float* gamma= (const float*)d_in[10];
    float* out = (float*)d_out;

    const int mlp_smem = (64 * RS + 64 * 128 + 128 * RS + 128 * 16) * (int)sizeof(float);
    static bool attr_done = false;
    const int edge_smem = (EPB * RAW_STRIDE * 4 + 24 * EPB) * (int)sizeof(float)
                          + 2 * EPB * (int)sizeof(int) + L_DIM * R_DIM * (int)sizeof(float);
    if (!attr_done) {
        cudaFuncSetAttribute(mlp_kernel, cudaFuncAttributeMaxDynamicSharedMemorySize, mlp_smem);
        cudaFuncSetAttribute(edge_kernel, cudaFuncAttributeMaxDynamicSharedMemorySize, edge_smem);
        attr_done = true;
    }

    const int blocks1 = (M_ROWS + MLP_ROWS - 1) / MLP_ROWS;
    mlp_kernel<<<blocks1, 512, mlp_smem>>>(X, W1s, b1s, W2s, b2s, W1d, b1d, W2d, b2d);

    const int blocks2 = E_EDGES / EPB;
    edge_kernel<<<blocks2, 256, edge_smem>>>(eidx, gamma, out);
}

// round 5
// speedup vs baseline: 2.2198x; 2.0443x over previous
#include <cuda_runtime.h>
#include <cstddef>
#include <cstdint>

#define N_NODES 50000
#define C_DIM   64
#define HID_DIM 128
#define R_DIM   16
#define B_DIM   2
#define L_DIM   12
#define E_EDGES 1600000
#define T_DIM   8
#define M_ROWS  (B_DIM * N_NODES)   // 100000

// Tables laid out [node][batch][16 floats] so one node's both batches = 128B line.
__device__ __align__(128) float4 g_a[M_ROWS * 4];
__device__ __align__(128) float4 g_b[M_ROWS * 4];

__device__ __forceinline__ uint32_t f2tf(float x) {
    uint32_t r;
    asm("cvt.rna.tf32.f32 %0, %1;" : "=r"(r) : "f"(x));
    return r;
}

__device__ __forceinline__ void mma_tf32(float* d, const uint32_t* a, uint32_t b0, uint32_t b1) {
    asm volatile(
        "mma.sync.aligned.m16n8k8.row.col.f32.tf32.tf32.f32 "
        "{%0,%1,%2,%3}, {%4,%5,%6,%7}, {%8,%9}, {%0,%1,%2,%3};"
        : "+f"(d[0]), "+f"(d[1]), "+f"(d[2]), "+f"(d[3])
        : "r"(a[0]), "r"(a[1]), "r"(a[2]), "r"(a[3]), "r"(b0), "r"(b1));
}

// ---------------------------------------------------------------------------
// Kernel 1: tf32 tensor-core MLP. 128-row tile, 256 threads (8 warps).
// Layer1: M128 N128 K64.  Warp = 32 rows x 64 cols (2 m-tiles x 8 n-tiles).
// Layer2: M128 N16  K128. Warp = 16 rows (1 m-tile x 2 n-tiles).
// ---------------------------------------------------------------------------
#define HS1 68    // stride (floats) for Hsm / Wsm   (68 mod 32 = 4 -> conflict-free frags)
#define HS2 132   // stride (floats) for Hid / W2sm  (132 mod 32 = 4)

__global__ __launch_bounds__(256, 1)
void mlp_kernel(const float* __restrict__ X,
                const float* __restrict__ W1s, const float* __restrict__ b1s,
                const float* __restrict__ W2s, const float* __restrict__ b2s,
                const float* __restrict__ W1d, const float* __restrict__ b1d,
                const float* __restrict__ W2d, const float* __restrict__ b2d)
{
    extern __shared__ float sh[];
    float* Hsm  = sh;                    // [128][HS1]  H tile (tf32 bits), row x k
    float* Wsm  = Hsm + 128 * HS1;       // [128][HS1]  W1 transposed: [n][k]
    float* Hid  = Wsm + 128 * HS1;       // [128][HS2]  hidden (tf32 bits), row x k
    float* W2sm = Hid + 128 * HS2;       // [16][HS2]   W2 transposed: [r][k]

    const int tid  = threadIdx.x;
    const int lane = tid & 31;
    const int warp = tid >> 5;
    const int g    = lane >> 2;   // 0..7
    const int t    = lane & 3;    // 0..3
    const int m0   = blockIdx.x * 128;

    // Stage H tile (tf32-rounded)
    #pragma unroll
    for (int u = 0; u < 8; u++) {
        int id = tid + 256 * u;          // 2048 float4
        int r  = id >> 4, cg = id & 15;
        int m  = m0 + r;
        float4 v = make_float4(0.f, 0.f, 0.f, 0.f);
        if (m < M_ROWS) {
            int b = m / N_NODES;
            int n = m - b * N_NODES;
            v = *(const float4*)&X[(((size_t)b * T_DIM + (T_DIM - 1)) * N_NODES + n) * C_DIM + cg * 4];
        }
        uint32_t* dst = (uint32_t*)&Hsm[r * HS1 + cg * 4];
        dst[0] = f2tf(v.x); dst[1] = f2tf(v.y); dst[2] = f2tf(v.z); dst[3] = f2tf(v.w);
    }

    for (int set = 0; set < 2; set++) {
        const float* W1 = set ? W1d : W1s;
        const float* b1 = set ? b1d : b1s;
        const float* W2 = set ? W2d : W2s;
        const float* b2 = set ? b2d : b2s;
        float4* outTab  = set ? g_b : g_a;

        // Stage W1 transposed -> Wsm[n][k]
        #pragma unroll
        for (int u = 0; u < 8; u++) {
            int id = tid + 256 * u;      // 2048 float4 of W1 [64][128]
            int k = id >> 5, ng = id & 31;
            float4 v = *(const float4*)&W1[k * 128 + ng * 4];
            uint32_t* w = (uint32_t*)Wsm;
            w[(ng * 4 + 0) * HS1 + k] = f2tf(v.x);
            w[(ng * 4 + 1) * HS1 + k] = f2tf(v.y);
            w[(ng * 4 + 2) * HS1 + k] = f2tf(v.z);
            w[(ng * 4 + 3) * HS1 + k] = f2tf(v.w);
        }
        // Stage W2 transposed -> W2sm[r][k]
        #pragma unroll
        for (int u = 0; u < 2; u++) {
            int id = tid + 256 * u;      // 512 float4 of W2 [128][16]
            int k = id >> 2, ng = id & 3;
            float4 v = *(const float4*)&W2[k * 16 + ng * 4];
            uint32_t* w = (uint32_t*)W2sm;
            w[(ng * 4 + 0) * HS2 + k] = f2tf(v.x);
            w[(ng * 4 + 1) * HS2 + k] = f2tf(v.y);
            w[(ng * 4 + 2) * HS2 + k] = f2tf(v.z);
            w[(ng * 4 + 3) * HS2 + k] = f2tf(v.w);
        }
        __syncthreads();

        // -------- Layer 1 --------
        {
            const int mr = warp >> 1;     // 0..3: row block of 32
            const int nc = warp & 1;      // 0..1: col block of 64
            float acc[2][8][4];
            #pragma unroll
            for (int mt = 0; mt < 2; mt++)
                #pragma unroll
                for (int nt = 0; nt < 8; nt++)
                    #pragma unroll
                    for (int i = 0; i < 4; i++) acc[mt][nt][i] = 0.0f;

            const uint32_t* hp = (const uint32_t*)Hsm;
            const uint32_t* wp = (const uint32_t*)Wsm;

            #pragma unroll
            for (int ks = 0; ks < 8; ks++) {
                uint32_t a[2][4];
                #pragma unroll
                for (int mt = 0; mt < 2; mt++) {
                    int row = mr * 32 + mt * 16;
                    a[mt][0] = hp[(row + g)     * HS1 + ks * 8 + t];
                    a[mt][1] = hp[(row + g + 8) * HS1 + ks * 8 + t];
                    a[mt][2] = hp[(row + g)     * HS1 + ks * 8 + t + 4];
                    a[mt][3] = hp[(row + g + 8) * HS1 + ks * 8 + t + 4];
                }
                #pragma unroll
                for (int nt = 0; nt < 8; nt++) {
                    int n = nc * 64 + nt * 8 + g;
                    uint32_t b0 = wp[n * HS1 + ks * 8 + t];
                    uint32_t b1v = wp[n * HS1 + ks * 8 + t + 4];
                    mma_tf32(acc[0][nt], a[0], b0, b1v);
                    mma_tf32(acc[1][nt], a[1], b0, b1v);
                }
            }

            // bias + relu -> Hid (tf32 bits)
            uint32_t* hd = (uint32_t*)Hid;
            #pragma unroll
            for (int nt = 0; nt < 8; nt++) {
                int ncol = nc * 64 + nt * 8 + t * 2;
                float2 bb = __ldg((const float2*)&b1[ncol]);
                #pragma unroll
                for (int mt = 0; mt < 2; mt++) {
                    int row = mr * 32 + mt * 16;
                    float v0 = acc[mt][nt][0] + bb.x; v0 = v0 > 0.f ? v0 : 0.f;
                    float v1 = acc[mt][nt][1] + bb.y; v1 = v1 > 0.f ? v1 : 0.f;
                    float v2 = acc[mt][nt][2] + bb.x; v2 = v2 > 0.f ? v2 : 0.f;
                    float v3 = acc[mt][nt][3] + bb.y; v3 = v3 > 0.f ? v3 : 0.f;
                    hd[(row + g)     * HS2 + ncol]     = f2tf(v0);
                    hd[(row + g)     * HS2 + ncol + 1] = f2tf(v1);
                    hd[(row + g + 8) * HS2 + ncol]     = f2tf(v2);
                    hd[(row + g + 8) * HS2 + ncol + 1] = f2tf(v3);
                }
            }
        }
        __syncthreads();

        // -------- Layer 2 --------
        {
            float acc2[2][4];
            #pragma unroll
            for (int nt = 0; nt < 2; nt++)
                #pragma unroll
                for (int i = 0; i < 4; i++) acc2[nt][i] = 0.0f;

            const uint32_t* hd = (const uint32_t*)Hid;
            const uint32_t* wp = (const uint32_t*)W2sm;
            const int rowb = warp * 16;

            #pragma unroll
            for (int ks = 0; ks < 16; ks++) {
                uint32_t a[4];
                a[0] = hd[(rowb + g)     * HS2 + ks * 8 + t];
                a[1] = hd[(rowb + g + 8) * HS2 + ks * 8 + t];
                a[2] = hd[(rowb + g)     * HS2 + ks * 8 + t + 4];
                a[3] = hd[(rowb + g + 8) * HS2 + ks * 8 + t + 4];
                #pragma unroll
                for (int nt = 0; nt < 2; nt++) {
                    uint32_t b0 = wp[(nt * 8 + g) * HS2 + ks * 8 + t];
                    uint32_t b1v = wp[(nt * 8 + g) * HS2 + ks * 8 + t + 4];
                    mma_tf32(acc2[nt], a, b0, b1v);
                }
            }

            // epilogue: + b2, write g tables in [node][batch][16] layout
            #pragma unroll
            for (int nt = 0; nt < 2; nt++) {
                int r0 = nt * 8 + t * 2;
                float2 bb = __ldg((const float2*)&b2[r0]);
                int m = m0 + rowb + g;
                if (m < M_ROWS) {
                    int b = m / N_NODES, n = m - b * N_NODES;
                    float2 v; v.x = acc2[nt][0] + bb.x; v.y = acc2[nt][1] + bb.y;
                    *(float2*)((float*)outTab + ((size_t)n * 2 + b) * 16 + r0) = v;
                }
                m = m0 + rowb + g + 8;
                if (m < M_ROWS) {
                    int b = m / N_NODES, n = m - b * N_NODES;
                    float2 v; v.x = acc2[nt][2] + bb.x; v.y = acc2[nt][3] + bb.y;
                    *(float2*)((float*)outTab + ((size_t)n * 2 + b) * 16 + r0) = v;
                }
            }
        }
        __syncthreads();
    }
}

// ---------------------------------------------------------------------------
// Kernel 2: edge scoring. 128 edges/block, 256 threads.
// Gather: warp instr = 2 edges x one table -> 4 fully-used 128B lines.
// Compute: thread = (batch, edge); direct coalesced STG.32 stores.
// ---------------------------------------------------------------------------
#define EPB 128
#define RAW_STRIDE 17    // float4 per edge (16 + 1 pad)

__global__ __launch_bounds__(256)
void edge_kernel(const int* __restrict__ eidx,
                 const float* __restrict__ gamma,
                 float* __restrict__ out)
{
    __shared__ float4 raw[EPB * RAW_STRIDE];
    __shared__ int    sIJ[2 * EPB];
    __shared__ float  g[L_DIM * R_DIM];

    const int tid = threadIdx.x;
    const long long e0 = (long long)blockIdx.x * EPB;

    sIJ[tid] = (tid < EPB) ? eidx[e0 + tid]
                           : eidx[(size_t)E_EDGES + e0 + tid - EPB];
    if (tid < L_DIM * R_DIM) g[tid] = gamma[tid];
    __syncthreads();

    // Gather: 2048 float4, 8 per thread. sub = tab*8 + (b*4+q).
    {
        float4 regs[8];
        int    dsts[8];
        #pragma unroll
        for (int u = 0; u < 8; u++) {
            int gid  = tid + 256 * u;
            int edge = gid >> 4;
            int sub  = gid & 15;
            int tab  = sub >> 3;
            int k    = sub & 7;
            int node = sIJ[tab * EPB + edge];
            const float4* tbl = tab ? g_b : g_a;
            regs[u] = tbl[(size_t)node * 8 + k];
            dsts[u] = edge * RAW_STRIDE + sub;
        }
        #pragma unroll
        for (int u = 0; u < 8; u++) raw[dsts[u]] = regs[u];
    }
    __syncthreads();

    // Compute: thread -> (bb = tid>>7, e = tid&127). Direct stores.
    {
        int bb = tid >> 7;
        int e  = tid & 127;
        const float4* base = raw + e * RAW_STRIDE;

        float p[16];
        #pragma unroll
        for (int q = 0; q < 4; q++) {
            float4 av = base[bb * 4 + q];
            float4 bv = base[8 + bb * 4 + q];
            p[q * 4 + 0] = av.x * bv.x;
            p[q * 4 + 1] = av.y * bv.y;
            p[q * 4 + 2] = av.z * bv.z;
            p[q * 4 + 3] = av.w * bv.w;
        }

        float* o = out + (size_t)bb * L_DIM * E_EDGES + e0 + e;
        #pragma unroll
        for (int l = 0; l < L_DIM; l++) {
            float s = 0.0f;
            #pragma unroll
            for (int r = 0; r < R_DIM; r++) s += g[l * R_DIM + r] * p[r];
            o[(size_t)l * E_EDGES] = s;
        }
    }
}

// ---------------------------------------------------------------------------
// Launch
// ---------------------------------------------------------------------------
extern "C" void kernel_launch(void* const* d_in, const int* in_sizes, int n_in,
                              void* d_out, int out_size)
{
    const float* X    = (const float*)d_in[0];
    const int*   eidx = (const int*)d_in[1];
    const float* W1s  = (const float*)d_in[2];
    const float* b1s  = (const float*)d_in[3];
    const float* W2s  = (const float*)d_in[4];
    const float* b2s  = (const float*)d_in[5];
    const float* W1d  = (const float*)d_in[6];
    const float* b1d  = (const float*)d_in[7];
    const float* W2d  = (const float*)d_in[8];
    const float* b2d  = (const float*)d_in[9];
    const float* gamma= (const float*)d_in[10];
    float* out = (float*)d_out;

    const int mlp_smem = (128 * HS1 * 2 + 128 * HS2 + 16 * HS2) * (int)sizeof(float);
    static bool attr_done = false;
    if (!attr_done) {
        cudaFuncSetAttribute(mlp_kernel, cudaFuncAttributeMaxDynamicSharedMemorySize, mlp_smem);
        attr_done = true;
    }

    const int blocks1 = (M_ROWS + 127) / 128;
    mlp_kernel<<<blocks1, 256, mlp_smem>>>(X, W1s, b1s, W2s, b2s, W1d, b1d, W2d, b2d);

    const int blocks2 = E_EDGES / EPB;
    edge_kernel<<<blocks2, 256>>>(eidx, gamma, out);
}